// round 16
// baseline (speedup 1.0000x reference)
#include <cuda_runtime.h>
#include <math.h>

#define BB   4
#define NN   8192
#define KK   16
#define INC  3
#define EMB  64
#define HID  128
#define NTOT (BB*NN)        // 32768 nodes
#define ETOT (NTOT*KK)      // 524288 edges

// ---------------- scratch (static device globals; no allocations) ----------------
__device__ float g_emb1[NTOT*EMB];
__device__ float g_emb2[NTOT*EMB];
__device__ int   g_idx [NTOT*KK];
__device__ float g_sq  [NTOT];
__device__ float g_xT [(size_t)BB*EMB*NN];  // transposed features [g][t][i]
__device__ float g_d2 [(size_t)BB*NN*NN];   // 1 GiB pairwise-distance scratch

// ---------------- squared norms, d=3: sequential mul-then-add (XLA small-row) -------
__global__ __launch_bounds__(256) void sqnorm3_kernel(const float* __restrict__ x,
                                                      float* __restrict__ sq) {
    int i = blockIdx.x * blockDim.x + threadIdx.x;
    if (i < NTOT) {
        float v0 = x[(size_t)i*3+0], v1 = x[(size_t)i*3+1], v2 = x[(size_t)i*3+2];
        float s = __fmul_rn(v0, v0);
        s = __fadd_rn(s, __fmul_rn(v1, v1));
        s = __fadd_rn(s, __fmul_rn(v2, v2));
        sq[i] = s;
    }
}

// ---------------- squared norms, d=64: XLA-GPU warp-tree emulation ------------------
__global__ __launch_bounds__(256) void sqnorm64_kernel(const float* __restrict__ x,
                                                       float* __restrict__ sq) {
    int warp = (blockIdx.x * blockDim.x + threadIdx.x) >> 5;
    int l    = threadIdx.x & 31;
    if (warp >= NTOT) return;
    float2 v = reinterpret_cast<const float2*>(x + (size_t)warp*64)[l];
    float p = __fadd_rn(__fmul_rn(v.x, v.x), __fmul_rn(v.y, v.y));
    #pragma unroll
    for (int off = 16; off > 0; off >>= 1)
        p = __fadd_rn(p, __shfl_down_sync(0xffffffffu, p, off));
    if (l == 0) sq[warp] = p;
}

// ---------------- global transpose: x[g][i][t] -> xT[g][t][i] (layout-only) ---------
__global__ __launch_bounds__(256) void transpose_kernel(const float* __restrict__ x,
                                                        float* __restrict__ xT) {
    __shared__ float tile[32][33];
    int g  = blockIdx.z;
    int i0 = blockIdx.x * 32;          // node base
    int t0 = blockIdx.y * 32;          // dim base
    int lx = threadIdx.x, ly = threadIdx.y;   // 32 x 8
    #pragma unroll
    for (int r = ly; r < 32; r += 8)
        tile[r][lx] = x[((size_t)g*NN + i0 + r)*64 + t0 + lx];
    __syncthreads();
    #pragma unroll
    for (int r = ly; r < 32; r += 8)
        xT[((size_t)g*64 + t0 + r)*NN + i0 + lx] = tile[lx][r];
}

// ---------------- insertion helper: stable top-16 ascending (strict <) --------------
__device__ __forceinline__ void topk_insert(float d, int j, float* bd, int* bi) {
    if (d < bd[KK-1]) {
        float dc = d; int ic = j;
        #pragma unroll
        for (int t = 0; t < KK; ++t) {
            if (dc < bd[t]) {
                float td = bd[t]; bd[t] = dc; dc = td;
                int   ti = bi[t]; bi[t] = ic; ic = ti;
            }
        }
    }
}

// ---------------- kNN, d=3: sequential FMA dot (R8 version, tie-frozen) -------------
__global__ __launch_bounds__(128) void knn3_kernel(const float* __restrict__ x,
                                                   const float* __restrict__ sq,
                                                   int* __restrict__ idxo) {
    const int TILE = 128;
    __shared__ float xs[TILE*3];
    __shared__ float sqs[TILE];
    int g  = blockIdx.y;
    int il = blockIdx.x * 128 + threadIdx.x;
    const float* xg = x + (size_t)g*NN*3;
    float xi0 = xg[il*3+0], xi1 = xg[il*3+1], xi2 = xg[il*3+2];
    float sqi = sq[g*NN + il];

    float bd[KK]; int bi[KK];
    #pragma unroll
    for (int t = 0; t < KK; ++t) { bd[t] = 3.0e38f; bi[t] = 0; }

    for (int jt = 0; jt < NN; jt += TILE) {
        __syncthreads();
        for (int u = threadIdx.x; u < TILE*3; u += 128) xs[u] = xg[jt*3 + u];
        if (threadIdx.x < TILE) sqs[threadIdx.x] = sq[g*NN + jt + threadIdx.x];
        __syncthreads();
        #pragma unroll 4
        for (int jj = 0; jj < TILE; ++jj) {
            int j = jt + jj;
            float acc = 0.f;
            acc = __fmaf_rn(xi0, xs[jj*3+0], acc);
            acc = __fmaf_rn(xi1, xs[jj*3+1], acc);
            acc = __fmaf_rn(xi2, xs[jj*3+2], acc);
            float d = __fsub_rn(__fadd_rn(sqi, sqs[jj]), __fmul_rn(2.0f, acc));
            if (j != il) topk_insert(d, j, bd, bi);
        }
    }
    #pragma unroll
    for (int t = 0; t < KK; ++t) idxo[((size_t)g*NN + il)*KK + t] = bi[t];
}

// ---------------- pairwise d2 GEMM, d=64, symmetric (triangular grid) ----------------
__global__ __launch_bounds__(256) void dist_gemm_kernel(const float* __restrict__ xT,
                                                        const float* __restrict__ sq,
                                                        float* __restrict__ d2) {
    // triangular decode: tile = J*(J+1)/2 + I, I <= J (while-corrected => exact)
    int tt = blockIdx.x, g = blockIdx.y;
    int J = (int)((sqrtf(8.0f*tt + 1.0f) - 1.0f) * 0.5f);
    while ((J+1)*(J+2)/2 <= tt) ++J;
    while (J*(J+1)/2 > tt) --J;
    int I = tt - J*(J+1)/2;

    extern __shared__ float sm[];
    float* As = sm;            // [64][132]: As[t*132 + i]
    float* Bs = sm + 64*132;   // [64][132]

    int tid = threadIdx.x;
    int tx = tid & 15, ty = tid >> 4;

    const float* xg = xT + (size_t)g*64*NN;
    #pragma unroll
    for (int r = 0; r < 8; ++r) {
        int u = r*256 + tid;           // 0..2047
        int t = u >> 5, c4 = u & 31;   // dim, float4-chunk
        float4 va = *reinterpret_cast<const float4*>(&xg[(size_t)t*NN + I*128 + c4*4]);
        *reinterpret_cast<float4*>(&As[t*132 + c4*4]) = va;
        float4 vb = *reinterpret_cast<const float4*>(&xg[(size_t)t*NN + J*128 + c4*4]);
        *reinterpret_cast<float4*>(&Bs[t*132 + c4*4]) = vb;
    }
    __syncthreads();

    float acc[8][8];
    #pragma unroll
    for (int p = 0; p < 8; ++p)
        #pragma unroll
        for (int q = 0; q < 8; ++q) acc[p][q] = 0.f;

    #pragma unroll 8
    for (int t = 0; t < 64; ++t) {
        float4 a0 = *reinterpret_cast<const float4*>(&As[t*132 + ty*8]);
        float4 a1 = *reinterpret_cast<const float4*>(&As[t*132 + ty*8 + 4]);
        float4 b0 = *reinterpret_cast<const float4*>(&Bs[t*132 + tx*8]);
        float4 b1 = *reinterpret_cast<const float4*>(&Bs[t*132 + tx*8 + 4]);
        float a[8] = {a0.x,a0.y,a0.z,a0.w,a1.x,a1.y,a1.z,a1.w};
        float b[8] = {b0.x,b0.y,b0.z,b0.w,b1.x,b1.y,b1.z,b1.w};
        #pragma unroll
        for (int p = 0; p < 8; ++p)
            #pragma unroll
            for (int q = 0; q < 8; ++q)
                acc[p][q] = __fmaf_rn(a[p], b[q], acc[p][q]);
    }

    int i0 = I*128 + ty*8, j0 = J*128 + tx*8;
    float sqi[8], sqj[8];
    #pragma unroll
    for (int p = 0; p < 8; ++p) { sqi[p] = sq[g*NN + i0 + p]; sqj[p] = sq[g*NN + j0 + p]; }
    #pragma unroll
    for (int p = 0; p < 8; ++p)
        #pragma unroll
        for (int q = 0; q < 8; ++q)
            acc[p][q] = __fsub_rn(__fadd_rn(sqi[p], sqj[q]), __fmul_rn(2.0f, acc[p][q]));

    float* dg = d2 + (size_t)g*NN*NN;
    #pragma unroll
    for (int p = 0; p < 8; ++p) {
        float4 w0 = make_float4(acc[p][0], acc[p][1], acc[p][2], acc[p][3]);
        float4 w1 = make_float4(acc[p][4], acc[p][5], acc[p][6], acc[p][7]);
        *reinterpret_cast<float4*>(&dg[(size_t)(i0+p)*NN + j0])     = w0;
        *reinterpret_cast<float4*>(&dg[(size_t)(i0+p)*NN + j0 + 4]) = w1;
    }
    if (I != J) {
        #pragma unroll
        for (int q = 0; q < 8; ++q) {
            float4 v0 = make_float4(acc[0][q], acc[1][q], acc[2][q], acc[3][q]);
            float4 v1 = make_float4(acc[4][q], acc[5][q], acc[6][q], acc[7][q]);
            *reinterpret_cast<float4*>(&dg[(size_t)(j0+q)*NN + i0])     = v0;
            *reinterpret_cast<float4*>(&dg[(size_t)(j0+q)*NN + i0 + 4]) = v1;
        }
    }
}

// ---------------- warp-per-query top-16 scan with ballot filter ----------------
// Lane l loads candidate jt+l (coalesced). Candidates passing the (conservative,
// possibly stale) threshold are processed in ascending bit order = ascending j;
// every lane performs the identical insert on its replicated list, so lists stay
// lane-identical. topk_insert re-checks against the live threshold => bit-exact
// equivalence with the verified serial ascending-j scan.
__global__ __launch_bounds__(256) void knn_scan_kernel(const float* __restrict__ d2,
                                                       int* __restrict__ idxo) {
    int q  = (blockIdx.x * 256 + threadIdx.x) >> 5;   // one warp per query
    int l  = threadIdx.x & 31;
    int g  = q >> 13;                                 // / NN
    int ql = q & (NN-1);
    const float* row = d2 + (size_t)g*NN*NN + (size_t)ql*NN;

    float bd[KK]; int bi[KK];
    #pragma unroll
    for (int t = 0; t < KK; ++t) { bd[t] = 3.0e38f; bi[t] = 0; }

    for (int jt = 0; jt < NN; jt += 32) {
        float d = row[jt + l];
        bool pass = (d < bd[KK-1]) && (jt + l != ql);
        unsigned mask = __ballot_sync(0xffffffffu, pass);
        while (mask) {
            int k = __ffs(mask) - 1;
            mask &= mask - 1;
            float dk = __shfl_sync(0xffffffffu, d, k);
            topk_insert(dk, jt + k, bd, bi);   // all lanes identical
        }
    }
    if (l == 0) {
        #pragma unroll
        for (int t = 0; t < KK; ++t) idxo[(size_t)q*KK + t] = bi[t];
    }
}

// ---------------- EdgeConv (verified scalar version) ----------------
template<int D>
__global__ __launch_bounds__(128) void edgeconv_kernel(const float* __restrict__ x,
                                                       const int*   __restrict__ idx,
                                                       const float* __restrict__ w1,
                                                       const float* __restrict__ b1,
                                                       const float* __restrict__ w2,
                                                       const float* __restrict__ b2,
                                                       float* __restrict__ out) {
    extern __shared__ float smem[];
    const int WREG = ((KK*D + KK*64 + D + 3)/4)*4;
    float* sw1 = smem;                 // [2D,64]
    float* sw2 = sw1 + 2*D*64;         // [64,64]
    float* sb1 = sw2 + 4096;
    float* sb2 = sb1 + 64;
    float* wbase = sb2 + 64;
    __shared__ int sidx[4][KK];

    int tid = threadIdx.x, warp = tid >> 5, l = tid & 31;
    for (int u = tid; u < 2*D*64; u += 128) sw1[u] = w1[u];
    for (int u = tid; u < 4096;   u += 128) sw2[u] = w2[u];
    if (tid < 64) { sb1[tid] = b1[tid]; sb2[tid] = b2[tid]; }

    float* sdiff = wbase + warp*WREG;  // [KK,D]
    float* sh1   = sdiff + KK*D;       // [KK,64]
    float* sxi   = sh1 + KK*64;        // [D]

    int n = blockIdx.x*4 + warp;
    int g = n / NN, il = n % NN;
    const float* xg = x + (size_t)g*NN*D;
    if (l < KK) sidx[warp][l] = idx[(size_t)n*KK + l];
    for (int t = l; t < D; t += 32) sxi[t] = xg[(size_t)il*D + t];
    __syncthreads();

    for (int u = l; u < KK*D; u += 32) {
        int j = u / D, t = u - j*D;
        sdiff[u] = __fsub_rn(xg[(size_t)sidx[warp][j]*D + t], sxi[t]);
    }
    __syncwarp();

    float baseA = 0.f, baseC = 0.f;
    for (int t = 0; t < D; ++t) {
        float f = sxi[t];
        baseA = __fmaf_rn(f, sw1[t*64 + l],      baseA);
        baseC = __fmaf_rn(f, sw1[t*64 + l + 32], baseC);
    }

    #pragma unroll
    for (int jb = 0; jb < 2; ++jb) {
        float aA[8], aC[8];
        #pragma unroll
        for (int q = 0; q < 8; ++q) { aA[q] = baseA; aC[q] = baseC; }

        if (D % 4 == 0) {
            for (int t = 0; t < D; t += 4) {
                float wa0 = sw1[(D+t+0)*64+l],    wa1 = sw1[(D+t+1)*64+l];
                float wa2 = sw1[(D+t+2)*64+l],    wa3 = sw1[(D+t+3)*64+l];
                float wc0 = sw1[(D+t+0)*64+l+32], wc1 = sw1[(D+t+1)*64+l+32];
                float wc2 = sw1[(D+t+2)*64+l+32], wc3 = sw1[(D+t+3)*64+l+32];
                #pragma unroll
                for (int q = 0; q < 8; ++q) {
                    float4 f = *reinterpret_cast<const float4*>(&sdiff[(jb*8+q)*D + t]);
                    float a = aA[q], c = aC[q];
                    a = __fmaf_rn(f.x, wa0, a); a = __fmaf_rn(f.y, wa1, a);
                    a = __fmaf_rn(f.z, wa2, a); a = __fmaf_rn(f.w, wa3, a);
                    c = __fmaf_rn(f.x, wc0, c); c = __fmaf_rn(f.y, wc1, c);
                    c = __fmaf_rn(f.z, wc2, c); c = __fmaf_rn(f.w, wc3, c);
                    aA[q] = a; aC[q] = c;
                }
            }
        } else {
            for (int t = 0; t < D; ++t) {
                float wa = sw1[(D+t)*64+l], wc = sw1[(D+t)*64+l+32];
                #pragma unroll
                for (int q = 0; q < 8; ++q) {
                    float f = sdiff[(jb*8+q)*D + t];
                    aA[q] = __fmaf_rn(f, wa, aA[q]);
                    aC[q] = __fmaf_rn(f, wc, aC[q]);
                }
            }
        }
        #pragma unroll
        for (int q = 0; q < 8; ++q) {
            int j = jb*8 + q;
            sh1[j*64 + l]      = fmaxf(__fadd_rn(aA[q], sb1[l]),    0.f);
            sh1[j*64 + l + 32] = fmaxf(__fadd_rn(aC[q], sb1[l+32]), 0.f);
        }
    }
    __syncwarp();

    float mA = -3.0e38f, mC = -3.0e38f;
    #pragma unroll
    for (int jb = 0; jb < 2; ++jb) {
        float aA[8], aC[8];
        #pragma unroll
        for (int q = 0; q < 8; ++q) { aA[q] = 0.f; aC[q] = 0.f; }
        for (int k = 0; k < 64; k += 4) {
            float wa0 = sw2[(k+0)*64+l],    wa1 = sw2[(k+1)*64+l];
            float wa2 = sw2[(k+2)*64+l],    wa3 = sw2[(k+3)*64+l];
            float wc0 = sw2[(k+0)*64+l+32], wc1 = sw2[(k+1)*64+l+32];
            float wc2 = sw2[(k+2)*64+l+32], wc3 = sw2[(k+3)*64+l+32];
            #pragma unroll
            for (int q = 0; q < 8; ++q) {
                float4 h = *reinterpret_cast<const float4*>(&sh1[(jb*8+q)*64 + k]);
                float a = aA[q], c = aC[q];
                a = __fmaf_rn(h.x, wa0, a); a = __fmaf_rn(h.y, wa1, a);
                a = __fmaf_rn(h.z, wa2, a); a = __fmaf_rn(h.w, wa3, a);
                c = __fmaf_rn(h.x, wc0, c); c = __fmaf_rn(h.y, wc1, c);
                c = __fmaf_rn(h.z, wc2, c); c = __fmaf_rn(h.w, wc3, c);
                aA[q] = a; aC[q] = c;
            }
        }
        #pragma unroll
        for (int q = 0; q < 8; ++q) { mA = fmaxf(mA, aA[q]); mC = fmaxf(mC, aC[q]); }
    }
    out[(size_t)n*64 + l]      = __fadd_rn(mA, sb2[l]);
    out[(size_t)n*64 + l + 32] = __fadd_rn(mC, sb2[l+32]);
}

// ---------------- final per-edge MLP + edge_index emit (verified version) ----------
__global__ __launch_bounds__(128) void mlp_kernel(const float* __restrict__ emb,
                                                  const int*   __restrict__ idx,
                                                  const float* __restrict__ w1,
                                                  const float* __restrict__ b1,
                                                  const float* __restrict__ w2,
                                                  const float* __restrict__ b2,
                                                  float* __restrict__ out, int out_size) {
    extern __shared__ float smem[];
    const int WREG = KK*64 + 64;
    float* sw1 = smem;                // [128,128]
    float* sb1 = sw1 + 16384;
    float* sw2 = sb1 + 128;
    float* wbase = sw2 + 128;
    __shared__ int sidx[4][KK];

    int tid = threadIdx.x, warp = tid >> 5, l = tid & 31;
    for (int u = tid; u < 16384; u += 128) sw1[u] = w1[u];
    if (tid < 128) { sb1[tid] = b1[tid]; sw2[tid] = w2[tid]; }

    float* ssf = wbase + warp*WREG;   // [KK,64] src feats
    float* sdf = ssf + KK*64;         // [64] dst feat

    int n = blockIdx.x*4 + warp;
    int g = n / NN;
    if (l < KK) sidx[warp][l] = idx[(size_t)n*KK + l];
    sdf[l]      = emb[(size_t)n*64 + l];
    sdf[l + 32] = emb[(size_t)n*64 + l + 32];
    __syncthreads();

    for (int u = l; u < KK*64; u += 32) {
        int j = u >> 6, t = u & 63;
        ssf[u] = emb[((size_t)g*NN + sidx[warp][j])*64 + t];
    }
    __syncwarp();

    float db[4];
    #pragma unroll
    for (int q = 0; q < 4; ++q) db[q] = sb1[l + 32*q];
    for (int t = 0; t < 64; ++t) {
        float f = sdf[t];
        #pragma unroll
        for (int q = 0; q < 4; ++q) db[q] = __fmaf_rn(f, sw1[(64+t)*128 + l + 32*q], db[q]);
    }

    float acc[KK][4];
    #pragma unroll
    for (int j = 0; j < KK; ++j)
        #pragma unroll
        for (int q = 0; q < 4; ++q) acc[j][q] = 0.f;

    for (int t = 0; t < 64; t += 4) {
        float wv[4][4];
        #pragma unroll
        for (int dt = 0; dt < 4; ++dt)
            #pragma unroll
            for (int q = 0; q < 4; ++q) wv[dt][q] = sw1[(t+dt)*128 + l + 32*q];
        #pragma unroll
        for (int j = 0; j < KK; ++j) {
            float4 f = *reinterpret_cast<const float4*>(&ssf[j*64 + t]);
            #pragma unroll
            for (int q = 0; q < 4; ++q) {
                float a = acc[j][q];
                a = __fmaf_rn(f.x, wv[0][q], a);
                a = __fmaf_rn(f.y, wv[1][q], a);
                a = __fmaf_rn(f.z, wv[2][q], a);
                a = __fmaf_rn(f.w, wv[3][q], a);
                acc[j][q] = a;
            }
        }
    }

    float w2v[4];
    #pragma unroll
    for (int q = 0; q < 4; ++q) w2v[q] = sw2[l + 32*q];
    float b2s = b2[0];

    float myp = 0.f;
    #pragma unroll
    for (int j = 0; j < KK; ++j) {
        float p = 0.f;
        #pragma unroll
        for (int q = 0; q < 4; ++q) p += fmaxf(acc[j][q] + db[q], 0.f) * w2v[q];
        #pragma unroll
        for (int off = 16; off > 0; off >>= 1) p += __shfl_xor_sync(0xffffffffu, p, off);
        if (l == j) myp = p;
    }
    if (l < KK) {
        int e = n*KK + l;
        float z = myp + b2s;
        out[e] = 1.0f / (1.0f + expf(-z));
        if (out_size >= 3*ETOT) {
            out[ETOT   + e] = (float)(g*NN + sidx[warp][l]);
            out[2*ETOT + e] = (float)n;
        }
    }
}

// ---------------- launch ----------------
extern "C" void kernel_launch(void* const* d_in, const int* in_sizes, int n_in,
                              void* d_out, int out_size) {
    const float* x      = (const float*)d_in[0];
    // d_in[1] = batch (int64), unused (equal-sized graphs)
    const float* c1_w1  = (const float*)d_in[2];
    const float* c1_b1  = (const float*)d_in[3];
    const float* c1_w2  = (const float*)d_in[4];
    const float* c1_b2  = (const float*)d_in[5];
    const float* c2_w1  = (const float*)d_in[6];
    const float* c2_b1  = (const float*)d_in[7];
    const float* c2_w2  = (const float*)d_in[8];
    const float* c2_b2  = (const float*)d_in[9];
    const float* mlp_w1 = (const float*)d_in[10];
    const float* mlp_b1 = (const float*)d_in[11];
    const float* mlp_w2 = (const float*)d_in[12];
    const float* mlp_b2 = (const float*)d_in[13];
    float* out = (float*)d_out;

    float *emb1, *emb2, *sq, *d2, *xT; int *idx;
    cudaGetSymbolAddress((void**)&emb1, g_emb1);
    cudaGetSymbolAddress((void**)&emb2, g_emb2);
    cudaGetSymbolAddress((void**)&sq,   g_sq);
    cudaGetSymbolAddress((void**)&idx,  g_idx);
    cudaGetSymbolAddress((void**)&d2,   g_d2);
    cudaGetSymbolAddress((void**)&xT,   g_xT);

    const int WREG64 = ((KK*64 + KK*64 + 64 + 3)/4)*4;   // 2112 floats
    const int WREG3  = ((KK*3  + KK*64 + 3  + 3)/4)*4;   // 1076 floats
    size_t sm_ec64 = (size_t)(2*64*64 + 4096 + 128 + 4*WREG64) * 4;
    size_t sm_ec3  = (size_t)(2*3*64  + 4096 + 128 + 4*WREG3 ) * 4;
    size_t sm_mlp  = (size_t)(16384 + 128 + 128 + 4*(KK*64+64)) * 4;
    size_t sm_gemm = (size_t)(2*64*132) * 4;             // 67.6 KB

    cudaFuncSetAttribute(edgeconv_kernel<64>, cudaFuncAttributeMaxDynamicSharedMemorySize, (int)sm_ec64);
    cudaFuncSetAttribute(edgeconv_kernel<3>,  cudaFuncAttributeMaxDynamicSharedMemorySize, (int)sm_ec3);
    cudaFuncSetAttribute(mlp_kernel,          cudaFuncAttributeMaxDynamicSharedMemorySize, (int)sm_mlp);
    cudaFuncSetAttribute(dist_gemm_kernel,    cudaFuncAttributeMaxDynamicSharedMemorySize, (int)sm_gemm);

    dim3 knn_grid(NN/128, BB);
    dim3 gemm_grid((NN/128)*((NN/128)+1)/2, BB);          // 2080 x 4 triangular
    dim3 tr_grid(NN/32, 2, BB);
    dim3 tr_block(32, 8);

    // stage 1: kNN on raw x (d=3) -> EdgeConv1 -> emb1
    sqnorm3_kernel<<<NTOT/256, 256>>>(x, sq);
    knn3_kernel<<<knn_grid, 128>>>(x, sq, idx);
    edgeconv_kernel<3><<<NTOT/4, 128, sm_ec3>>>(x, idx, c1_w1, c1_b1, c1_w2, c1_b2, emb1);

    // stage 2: transpose + d2 GEMM + warp-ballot scan on emb1 -> EdgeConv2 -> emb2
    transpose_kernel<<<tr_grid, tr_block>>>(emb1, xT);
    sqnorm64_kernel<<<(NTOT*32)/256, 256>>>(emb1, sq);
    dist_gemm_kernel<<<gemm_grid, 256, sm_gemm>>>(xT, sq, d2);
    knn_scan_kernel<<<(NTOT*32)/256, 256>>>(d2, idx);
    edgeconv_kernel<64><<<NTOT/4, 128, sm_ec64>>>(emb1, idx, c2_w1, c2_b1, c2_w2, c2_b2, emb2);

    // stage 3: transpose + d2 GEMM + warp-ballot scan on emb2 -> per-edge MLP
    transpose_kernel<<<tr_grid, tr_block>>>(emb2, xT);
    sqnorm64_kernel<<<(NTOT*32)/256, 256>>>(emb2, sq);
    dist_gemm_kernel<<<gemm_grid, 256, sm_gemm>>>(xT, sq, d2);
    knn_scan_kernel<<<(NTOT*32)/256, 256>>>(d2, idx);
    mlp_kernel<<<NTOT/4, 128, sm_mlp>>>(emb2, idx, mlp_w1, mlp_b1, mlp_w2, mlp_b2, out, out_size);
}

// round 17
// speedup vs baseline: 1.8511x; 1.8511x over previous
#include <cuda_runtime.h>
#include <math.h>

#define BB   4
#define NN   8192
#define KK   16
#define INC  3
#define EMB  64
#define HID  128
#define NTOT (BB*NN)        // 32768 nodes
#define ETOT (NTOT*KK)      // 524288 edges

// ---------------- scratch (static device globals; no allocations) ----------------
__device__ float g_emb1[NTOT*EMB];
__device__ float g_emb2[NTOT*EMB];
__device__ int   g_idx [NTOT*KK];
__device__ float g_sq  [NTOT];
__device__ float g_xT [(size_t)BB*EMB*NN];  // transposed features [g][t][i]
__device__ float g_d2 [(size_t)BB*NN*NN];   // 1 GiB pairwise-distance scratch

// ---------------- squared norms, d=3: sequential mul-then-add (XLA small-row) -------
__global__ __launch_bounds__(256) void sqnorm3_kernel(const float* __restrict__ x,
                                                      float* __restrict__ sq) {
    int i = blockIdx.x * blockDim.x + threadIdx.x;
    if (i < NTOT) {
        float v0 = x[(size_t)i*3+0], v1 = x[(size_t)i*3+1], v2 = x[(size_t)i*3+2];
        float s = __fmul_rn(v0, v0);
        s = __fadd_rn(s, __fmul_rn(v1, v1));
        s = __fadd_rn(s, __fmul_rn(v2, v2));
        sq[i] = s;
    }
}

// ---------------- squared norms, d=64: XLA-GPU warp-tree emulation ------------------
__global__ __launch_bounds__(256) void sqnorm64_kernel(const float* __restrict__ x,
                                                       float* __restrict__ sq) {
    int warp = (blockIdx.x * blockDim.x + threadIdx.x) >> 5;
    int l    = threadIdx.x & 31;
    if (warp >= NTOT) return;
    float2 v = reinterpret_cast<const float2*>(x + (size_t)warp*64)[l];
    float p = __fadd_rn(__fmul_rn(v.x, v.x), __fmul_rn(v.y, v.y));
    #pragma unroll
    for (int off = 16; off > 0; off >>= 1)
        p = __fadd_rn(p, __shfl_down_sync(0xffffffffu, p, off));
    if (l == 0) sq[warp] = p;
}

// ---------------- global transpose: x[g][i][t] -> xT[g][t][i] (layout-only) ---------
__global__ __launch_bounds__(256) void transpose_kernel(const float* __restrict__ x,
                                                        float* __restrict__ xT) {
    __shared__ float tile[32][33];
    int g  = blockIdx.z;
    int i0 = blockIdx.x * 32;          // node base
    int t0 = blockIdx.y * 32;          // dim base
    int lx = threadIdx.x, ly = threadIdx.y;   // 32 x 8
    #pragma unroll
    for (int r = ly; r < 32; r += 8)
        tile[r][lx] = x[((size_t)g*NN + i0 + r)*64 + t0 + lx];
    __syncthreads();
    #pragma unroll
    for (int r = ly; r < 32; r += 8)
        xT[((size_t)g*64 + t0 + r)*NN + i0 + lx] = tile[lx][r];
}

// ---------------- insertion helper: stable top-16 ascending (strict <) --------------
__device__ __forceinline__ void topk_insert(float d, int j, float* bd, int* bi) {
    if (d < bd[KK-1]) {
        float dc = d; int ic = j;
        #pragma unroll
        for (int t = 0; t < KK; ++t) {
            if (dc < bd[t]) {
                float td = bd[t]; bd[t] = dc; dc = td;
                int   ti = bi[t]; bi[t] = ic; ic = ti;
            }
        }
    }
}

// ---------------- kNN, d=3: sequential FMA dot (R8 version, tie-frozen) -------------
__global__ __launch_bounds__(128) void knn3_kernel(const float* __restrict__ x,
                                                   const float* __restrict__ sq,
                                                   int* __restrict__ idxo) {
    const int TILE = 128;
    __shared__ float xs[TILE*3];
    __shared__ float sqs[TILE];
    int g  = blockIdx.y;
    int il = blockIdx.x * 128 + threadIdx.x;
    const float* xg = x + (size_t)g*NN*3;
    float xi0 = xg[il*3+0], xi1 = xg[il*3+1], xi2 = xg[il*3+2];
    float sqi = sq[g*NN + il];

    float bd[KK]; int bi[KK];
    #pragma unroll
    for (int t = 0; t < KK; ++t) { bd[t] = 3.0e38f; bi[t] = 0; }

    for (int jt = 0; jt < NN; jt += TILE) {
        __syncthreads();
        for (int u = threadIdx.x; u < TILE*3; u += 128) xs[u] = xg[jt*3 + u];
        if (threadIdx.x < TILE) sqs[threadIdx.x] = sq[g*NN + jt + threadIdx.x];
        __syncthreads();
        #pragma unroll 4
        for (int jj = 0; jj < TILE; ++jj) {
            int j = jt + jj;
            float acc = 0.f;
            acc = __fmaf_rn(xi0, xs[jj*3+0], acc);
            acc = __fmaf_rn(xi1, xs[jj*3+1], acc);
            acc = __fmaf_rn(xi2, xs[jj*3+2], acc);
            float d = __fsub_rn(__fadd_rn(sqi, sqs[jj]), __fmul_rn(2.0f, acc));
            if (j != il) topk_insert(d, j, bd, bi);
        }
    }
    #pragma unroll
    for (int t = 0; t < KK; ++t) idxo[((size_t)g*NN + il)*KK + t] = bi[t];
}

// ---------------- pairwise d2 GEMM, d=64, symmetric (triangular grid, xT input) ------
__global__ __launch_bounds__(256) void dist_gemm_kernel(const float* __restrict__ xT,
                                                        const float* __restrict__ sq,
                                                        float* __restrict__ d2) {
    // triangular decode: tile = J*(J+1)/2 + I, I <= J (while-corrected => exact)
    int tt = blockIdx.x, g = blockIdx.y;
    int J = (int)((sqrtf(8.0f*tt + 1.0f) - 1.0f) * 0.5f);
    while ((J+1)*(J+2)/2 <= tt) ++J;
    while (J*(J+1)/2 > tt) --J;
    int I = tt - J*(J+1)/2;

    extern __shared__ float sm[];
    float* As = sm;            // [64][132]: As[t*132 + i]
    float* Bs = sm + 64*132;   // [64][132]

    int tid = threadIdx.x;
    int tx = tid & 15, ty = tid >> 4;

    const float* xg = xT + (size_t)g*64*NN;
    #pragma unroll
    for (int r = 0; r < 8; ++r) {
        int u = r*256 + tid;           // 0..2047
        int t = u >> 5, c4 = u & 31;   // dim, float4-chunk
        float4 va = *reinterpret_cast<const float4*>(&xg[(size_t)t*NN + I*128 + c4*4]);
        *reinterpret_cast<float4*>(&As[t*132 + c4*4]) = va;
        float4 vb = *reinterpret_cast<const float4*>(&xg[(size_t)t*NN + J*128 + c4*4]);
        *reinterpret_cast<float4*>(&Bs[t*132 + c4*4]) = vb;
    }
    __syncthreads();

    float acc[8][8];
    #pragma unroll
    for (int p = 0; p < 8; ++p)
        #pragma unroll
        for (int q = 0; q < 8; ++q) acc[p][q] = 0.f;

    #pragma unroll 8
    for (int t = 0; t < 64; ++t) {
        float4 a0 = *reinterpret_cast<const float4*>(&As[t*132 + ty*8]);
        float4 a1 = *reinterpret_cast<const float4*>(&As[t*132 + ty*8 + 4]);
        float4 b0 = *reinterpret_cast<const float4*>(&Bs[t*132 + tx*8]);
        float4 b1 = *reinterpret_cast<const float4*>(&Bs[t*132 + tx*8 + 4]);
        float a[8] = {a0.x,a0.y,a0.z,a0.w,a1.x,a1.y,a1.z,a1.w};
        float b[8] = {b0.x,b0.y,b0.z,b0.w,b1.x,b1.y,b1.z,b1.w};
        #pragma unroll
        for (int p = 0; p < 8; ++p)
            #pragma unroll
            for (int q = 0; q < 8; ++q)
                acc[p][q] = __fmaf_rn(a[p], b[q], acc[p][q]);
    }

    int i0 = I*128 + ty*8, j0 = J*128 + tx*8;
    float sqi[8], sqj[8];
    #pragma unroll
    for (int p = 0; p < 8; ++p) { sqi[p] = sq[g*NN + i0 + p]; sqj[p] = sq[g*NN + j0 + p]; }
    #pragma unroll
    for (int p = 0; p < 8; ++p)
        #pragma unroll
        for (int q = 0; q < 8; ++q)
            acc[p][q] = __fsub_rn(__fadd_rn(sqi[p], sqj[q]), __fmul_rn(2.0f, acc[p][q]));

    float* dg = d2 + (size_t)g*NN*NN;
    #pragma unroll
    for (int p = 0; p < 8; ++p) {
        float4 w0 = make_float4(acc[p][0], acc[p][1], acc[p][2], acc[p][3]);
        float4 w1 = make_float4(acc[p][4], acc[p][5], acc[p][6], acc[p][7]);
        *reinterpret_cast<float4*>(&dg[(size_t)(i0+p)*NN + j0])     = w0;
        *reinterpret_cast<float4*>(&dg[(size_t)(i0+p)*NN + j0 + 4]) = w1;
    }
    if (I != J) {
        #pragma unroll
        for (int q = 0; q < 8; ++q) {
            float4 v0 = make_float4(acc[0][q], acc[1][q], acc[2][q], acc[3][q]);
            float4 v1 = make_float4(acc[4][q], acc[5][q], acc[6][q], acc[7][q]);
            *reinterpret_cast<float4*>(&dg[(size_t)(j0+q)*NN + i0])     = v0;
            *reinterpret_cast<float4*>(&dg[(size_t)(j0+q)*NN + i0 + 4]) = v1;
        }
    }
}

// ---------------- monolithic top-16 scan (exact R10 body) + L2 prefetch -------------
// Identical loads, gate, and insert order to the verified R10 scan; the only
// addition is a non-binding prefetch.global.L2 hint 256 candidates ahead.
__global__ __launch_bounds__(128) void knn_scan_kernel(const float* __restrict__ d2,
                                                       int* __restrict__ idxo) {
    int q  = blockIdx.x * 128 + threadIdx.x;   // global query
    int g  = q >> 13;                          // / NN
    int ql = q & (NN-1);
    const float4* row = reinterpret_cast<const float4*>(
        d2 + (size_t)g*NN*NN + (size_t)ql*NN);

    float bd[KK]; int bi[KK];
    #pragma unroll
    for (int t = 0; t < KK; ++t) { bd[t] = 3.0e38f; bi[t] = 0; }

    // software pipeline: next group's loads in flight while gating current group
    float4 n0 = row[0], n1 = row[1], n2 = row[2], n3 = row[3];
    for (int jt = 0; jt < NN; jt += 16) {
        if (jt + 256 < NN) {
            const float4* pf = row + ((jt + 256) >> 2);
            asm volatile("prefetch.global.L2 [%0];" :: "l"(pf));
        }
        float4 v0 = n0, v1 = n1, v2 = n2, v3 = n3;
        if (jt + 16 < NN) {
            int b = (jt >> 2) + 4;
            n0 = row[b]; n1 = row[b+1]; n2 = row[b+2]; n3 = row[b+3];
        }
        float m0 = fminf(fminf(v0.x, v0.y), fminf(v0.z, v0.w));
        float m1 = fminf(fminf(v1.x, v1.y), fminf(v1.z, v1.w));
        float m2 = fminf(fminf(v2.x, v2.y), fminf(v2.z, v2.w));
        float m3 = fminf(fminf(v3.x, v3.y), fminf(v3.z, v3.w));
        float m  = fminf(fminf(m0, m1), fminf(m2, m3));
        if (m < bd[KK-1]) {           // rare path: exact per-candidate, ascending j
            float c[16] = {v0.x,v0.y,v0.z,v0.w, v1.x,v1.y,v1.z,v1.w,
                           v2.x,v2.y,v2.z,v2.w, v3.x,v3.y,v3.z,v3.w};
            #pragma unroll
            for (int k = 0; k < 16; ++k) {
                int j = jt + k;
                if (j != ql) topk_insert(c[k], j, bd, bi);
            }
        }
    }
    #pragma unroll
    for (int t = 0; t < KK; ++t) idxo[(size_t)q*KK + t] = bi[t];
}

// ---------------- EdgeConv (verified scalar version) ----------------
template<int D>
__global__ __launch_bounds__(128) void edgeconv_kernel(const float* __restrict__ x,
                                                       const int*   __restrict__ idx,
                                                       const float* __restrict__ w1,
                                                       const float* __restrict__ b1,
                                                       const float* __restrict__ w2,
                                                       const float* __restrict__ b2,
                                                       float* __restrict__ out) {
    extern __shared__ float smem[];
    const int WREG = ((KK*D + KK*64 + D + 3)/4)*4;
    float* sw1 = smem;                 // [2D,64]
    float* sw2 = sw1 + 2*D*64;         // [64,64]
    float* sb1 = sw2 + 4096;
    float* sb2 = sb1 + 64;
    float* wbase = sb2 + 64;
    __shared__ int sidx[4][KK];

    int tid = threadIdx.x, warp = tid >> 5, l = tid & 31;
    for (int u = tid; u < 2*D*64; u += 128) sw1[u] = w1[u];
    for (int u = tid; u < 4096;   u += 128) sw2[u] = w2[u];
    if (tid < 64) { sb1[tid] = b1[tid]; sb2[tid] = b2[tid]; }

    float* sdiff = wbase + warp*WREG;  // [KK,D]
    float* sh1   = sdiff + KK*D;       // [KK,64]
    float* sxi   = sh1 + KK*64;        // [D]

    int n = blockIdx.x*4 + warp;
    int g = n / NN, il = n % NN;
    const float* xg = x + (size_t)g*NN*D;
    if (l < KK) sidx[warp][l] = idx[(size_t)n*KK + l];
    for (int t = l; t < D; t += 32) sxi[t] = xg[(size_t)il*D + t];
    __syncthreads();

    for (int u = l; u < KK*D; u += 32) {
        int j = u / D, t = u - j*D;
        sdiff[u] = __fsub_rn(xg[(size_t)sidx[warp][j]*D + t], sxi[t]);
    }
    __syncwarp();

    float baseA = 0.f, baseC = 0.f;
    for (int t = 0; t < D; ++t) {
        float f = sxi[t];
        baseA = __fmaf_rn(f, sw1[t*64 + l],      baseA);
        baseC = __fmaf_rn(f, sw1[t*64 + l + 32], baseC);
    }

    #pragma unroll
    for (int jb = 0; jb < 2; ++jb) {
        float aA[8], aC[8];
        #pragma unroll
        for (int q = 0; q < 8; ++q) { aA[q] = baseA; aC[q] = baseC; }

        if (D % 4 == 0) {
            for (int t = 0; t < D; t += 4) {
                float wa0 = sw1[(D+t+0)*64+l],    wa1 = sw1[(D+t+1)*64+l];
                float wa2 = sw1[(D+t+2)*64+l],    wa3 = sw1[(D+t+3)*64+l];
                float wc0 = sw1[(D+t+0)*64+l+32], wc1 = sw1[(D+t+1)*64+l+32];
                float wc2 = sw1[(D+t+2)*64+l+32], wc3 = sw1[(D+t+3)*64+l+32];
                #pragma unroll
                for (int q = 0; q < 8; ++q) {
                    float4 f = *reinterpret_cast<const float4*>(&sdiff[(jb*8+q)*D + t]);
                    float a = aA[q], c = aC[q];
                    a = __fmaf_rn(f.x, wa0, a); a = __fmaf_rn(f.y, wa1, a);
                    a = __fmaf_rn(f.z, wa2, a); a = __fmaf_rn(f.w, wa3, a);
                    c = __fmaf_rn(f.x, wc0, c); c = __fmaf_rn(f.y, wc1, c);
                    c = __fmaf_rn(f.z, wc2, c); c = __fmaf_rn(f.w, wc3, c);
                    aA[q] = a; aC[q] = c;
                }
            }
        } else {
            for (int t = 0; t < D; ++t) {
                float wa = sw1[(D+t)*64+l], wc = sw1[(D+t)*64+l+32];
                #pragma unroll
                for (int q = 0; q < 8; ++q) {
                    float f = sdiff[(jb*8+q)*D + t];
                    aA[q] = __fmaf_rn(f, wa, aA[q]);
                    aC[q] = __fmaf_rn(f, wc, aC[q]);
                }
            }
        }
        #pragma unroll
        for (int q = 0; q < 8; ++q) {
            int j = jb*8 + q;
            sh1[j*64 + l]      = fmaxf(__fadd_rn(aA[q], sb1[l]),    0.f);
            sh1[j*64 + l + 32] = fmaxf(__fadd_rn(aC[q], sb1[l+32]), 0.f);
        }
    }
    __syncwarp();

    float mA = -3.0e38f, mC = -3.0e38f;
    #pragma unroll
    for (int jb = 0; jb < 2; ++jb) {
        float aA[8], aC[8];
        #pragma unroll
        for (int q = 0; q < 8; ++q) { aA[q] = 0.f; aC[q] = 0.f; }
        for (int k = 0; k < 64; k += 4) {
            float wa0 = sw2[(k+0)*64+l],    wa1 = sw2[(k+1)*64+l];
            float wa2 = sw2[(k+2)*64+l],    wa3 = sw2[(k+3)*64+l];
            float wc0 = sw2[(k+0)*64+l+32], wc1 = sw2[(k+1)*64+l+32];
            float wc2 = sw2[(k+2)*64+l+32], wc3 = sw2[(k+3)*64+l+32];
            #pragma unroll
            for (int q = 0; q < 8; ++q) {
                float4 h = *reinterpret_cast<const float4*>(&sh1[(jb*8+q)*64 + k]);
                float a = aA[q], c = aC[q];
                a = __fmaf_rn(h.x, wa0, a); a = __fmaf_rn(h.y, wa1, a);
                a = __fmaf_rn(h.z, wa2, a); a = __fmaf_rn(h.w, wa3, a);
                c = __fmaf_rn(h.x, wc0, c); c = __fmaf_rn(h.y, wc1, c);
                c = __fmaf_rn(h.z, wc2, c); c = __fmaf_rn(h.w, wc3, c);
                aA[q] = a; aC[q] = c;
            }
        }
        #pragma unroll
        for (int q = 0; q < 8; ++q) { mA = fmaxf(mA, aA[q]); mC = fmaxf(mC, aC[q]); }
    }
    out[(size_t)n*64 + l]      = __fadd_rn(mA, sb2[l]);
    out[(size_t)n*64 + l + 32] = __fadd_rn(mC, sb2[l+32]);
}

// ---------------- final per-edge MLP + edge_index emit (verified version) ----------
__global__ __launch_bounds__(128) void mlp_kernel(const float* __restrict__ emb,
                                                  const int*   __restrict__ idx,
                                                  const float* __restrict__ w1,
                                                  const float* __restrict__ b1,
                                                  const float* __restrict__ w2,
                                                  const float* __restrict__ b2,
                                                  float* __restrict__ out, int out_size) {
    extern __shared__ float smem[];
    const int WREG = KK*64 + 64;
    float* sw1 = smem;                // [128,128]
    float* sb1 = sw1 + 16384;
    float* sw2 = sb1 + 128;
    float* wbase = sw2 + 128;
    __shared__ int sidx[4][KK];

    int tid = threadIdx.x, warp = tid >> 5, l = tid & 31;
    for (int u = tid; u < 16384; u += 128) sw1[u] = w1[u];
    if (tid < 128) { sb1[tid] = b1[tid]; sw2[tid] = w2[tid]; }

    float* ssf = wbase + warp*WREG;   // [KK,64] src feats
    float* sdf = ssf + KK*64;         // [64] dst feat

    int n = blockIdx.x*4 + warp;
    int g = n / NN;
    if (l < KK) sidx[warp][l] = idx[(size_t)n*KK + l];
    sdf[l]      = emb[(size_t)n*64 + l];
    sdf[l + 32] = emb[(size_t)n*64 + l + 32];
    __syncthreads();

    for (int u = l; u < KK*64; u += 32) {
        int j = u >> 6, t = u & 63;
        ssf[u] = emb[((size_t)g*NN + sidx[warp][j])*64 + t];
    }
    __syncwarp();

    float db[4];
    #pragma unroll
    for (int q = 0; q < 4; ++q) db[q] = sb1[l + 32*q];
    for (int t = 0; t < 64; ++t) {
        float f = sdf[t];
        #pragma unroll
        for (int q = 0; q < 4; ++q) db[q] = __fmaf_rn(f, sw1[(64+t)*128 + l + 32*q], db[q]);
    }

    float acc[KK][4];
    #pragma unroll
    for (int j = 0; j < KK; ++j)
        #pragma unroll
        for (int q = 0; q < 4; ++q) acc[j][q] = 0.f;

    for (int t = 0; t < 64; t += 4) {
        float wv[4][4];
        #pragma unroll
        for (int dt = 0; dt < 4; ++dt)
            #pragma unroll
            for (int q = 0; q < 4; ++q) wv[dt][q] = sw1[(t+dt)*128 + l + 32*q];
        #pragma unroll
        for (int j = 0; j < KK; ++j) {
            float4 f = *reinterpret_cast<const float4*>(&ssf[j*64 + t]);
            #pragma unroll
            for (int q = 0; q < 4; ++q) {
                float a = acc[j][q];
                a = __fmaf_rn(f.x, wv[0][q], a);
                a = __fmaf_rn(f.y, wv[1][q], a);
                a = __fmaf_rn(f.z, wv[2][q], a);
                a = __fmaf_rn(f.w, wv[3][q], a);
                acc[j][q] = a;
            }
        }
    }

    float w2v[4];
    #pragma unroll
    for (int q = 0; q < 4; ++q) w2v[q] = sw2[l + 32*q];
    float b2s = b2[0];

    float myp = 0.f;
    #pragma unroll
    for (int j = 0; j < KK; ++j) {
        float p = 0.f;
        #pragma unroll
        for (int q = 0; q < 4; ++q) p += fmaxf(acc[j][q] + db[q], 0.f) * w2v[q];
        #pragma unroll
        for (int off = 16; off > 0; off >>= 1) p += __shfl_xor_sync(0xffffffffu, p, off);
        if (l == j) myp = p;
    }
    if (l < KK) {
        int e = n*KK + l;
        float z = myp + b2s;
        out[e] = 1.0f / (1.0f + expf(-z));
        if (out_size >= 3*ETOT) {
            out[ETOT   + e] = (float)(g*NN + sidx[warp][l]);
            out[2*ETOT + e] = (float)n;
        }
    }
}

// ---------------- launch ----------------
extern "C" void kernel_launch(void* const* d_in, const int* in_sizes, int n_in,
                              void* d_out, int out_size) {
    const float* x      = (const float*)d_in[0];
    // d_in[1] = batch (int64), unused (equal-sized graphs)
    const float* c1_w1  = (const float*)d_in[2];
    const float* c1_b1  = (const float*)d_in[3];
    const float* c1_w2  = (const float*)d_in[4];
    const float* c1_b2  = (const float*)d_in[5];
    const float* c2_w1  = (const float*)d_in[6];
    const float* c2_b1  = (const float*)d_in[7];
    const float* c2_w2  = (const float*)d_in[8];
    const float* c2_b2  = (const float*)d_in[9];
    const float* mlp_w1 = (const float*)d_in[10];
    const float* mlp_b1 = (const float*)d_in[11];
    const float* mlp_w2 = (const float*)d_in[12];
    const float* mlp_b2 = (const float*)d_in[13];
    float* out = (float*)d_out;

    float *emb1, *emb2, *sq, *d2, *xT; int *idx;
    cudaGetSymbolAddress((void**)&emb1, g_emb1);
    cudaGetSymbolAddress((void**)&emb2, g_emb2);
    cudaGetSymbolAddress((void**)&sq,   g_sq);
    cudaGetSymbolAddress((void**)&idx,  g_idx);
    cudaGetSymbolAddress((void**)&d2,   g_d2);
    cudaGetSymbolAddress((void**)&xT,   g_xT);

    const int WREG64 = ((KK*64 + KK*64 + 64 + 3)/4)*4;   // 2112 floats
    const int WREG3  = ((KK*3  + KK*64 + 3  + 3)/4)*4;   // 1076 floats
    size_t sm_ec64 = (size_t)(2*64*64 + 4096 + 128 + 4*WREG64) * 4;
    size_t sm_ec3  = (size_t)(2*3*64  + 4096 + 128 + 4*WREG3 ) * 4;
    size_t sm_mlp  = (size_t)(16384 + 128 + 128 + 4*(KK*64+64)) * 4;
    size_t sm_gemm = (size_t)(2*64*132) * 4;             // 67.6 KB

    cudaFuncSetAttribute(edgeconv_kernel<64>, cudaFuncAttributeMaxDynamicSharedMemorySize, (int)sm_ec64);
    cudaFuncSetAttribute(edgeconv_kernel<3>,  cudaFuncAttributeMaxDynamicSharedMemorySize, (int)sm_ec3);
    cudaFuncSetAttribute(mlp_kernel,          cudaFuncAttributeMaxDynamicSharedMemorySize, (int)sm_mlp);
    cudaFuncSetAttribute(dist_gemm_kernel,    cudaFuncAttributeMaxDynamicSharedMemorySize, (int)sm_gemm);

    dim3 knn_grid(NN/128, BB);
    dim3 gemm_grid((NN/128)*((NN/128)+1)/2, BB);          // 2080 x 4 triangular
    dim3 tr_grid(NN/32, 2, BB);
    dim3 tr_block(32, 8);

    // stage 1: kNN on raw x (d=3) -> EdgeConv1 -> emb1
    sqnorm3_kernel<<<NTOT/256, 256>>>(x, sq);
    knn3_kernel<<<knn_grid, 128>>>(x, sq, idx);
    edgeconv_kernel<3><<<NTOT/4, 128, sm_ec3>>>(x, idx, c1_w1, c1_b1, c1_w2, c1_b2, emb1);

    // stage 2: transpose + d2 GEMM + gated scan (L2 prefetch) on emb1 -> EdgeConv2
    transpose_kernel<<<tr_grid, tr_block>>>(emb1, xT);
    sqnorm64_kernel<<<(NTOT*32)/256, 256>>>(emb1, sq);
    dist_gemm_kernel<<<gemm_grid, 256, sm_gemm>>>(xT, sq, d2);
    knn_scan_kernel<<<NTOT/128, 128>>>(d2, idx);
    edgeconv_kernel<64><<<NTOT/4, 128, sm_ec64>>>(emb1, idx, c2_w1, c2_b1, c2_w2, c2_b2, emb2);

    // stage 3: transpose + d2 GEMM + gated scan (L2 prefetch) on emb2 -> MLP
    transpose_kernel<<<tr_grid, tr_block>>>(emb2, xT);
    sqnorm64_kernel<<<(NTOT*32)/256, 256>>>(emb2, sq);
    dist_gemm_kernel<<<gemm_grid, 256, sm_gemm>>>(xT, sq, d2);
    knn_scan_kernel<<<NTOT/128, 128>>>(d2, idx);
    mlp_kernel<<<NTOT/4, 128, sm_mlp>>>(emb2, idx, mlp_w1, mlp_b1, mlp_w2, mlp_b2, out, out_size);
}